// round 9
// baseline (speedup 1.0000x reference)
#include <cuda_runtime.h>

// ---------------------------------------------------------------------------
// LearnableWaveletTransform, fused + s-register-tiled (RT=4 outputs/thread),
// with BALANCED warp->s mapping: each block holds one warp from each s-octant
// so per-block work is uniform (heavy level-3 warps are spread 1-per-block).
//
//   x: [B=8, S=4096, F=128] f32  ->  out: [6, B, 4096, F] f32
//   slots: [lo3, hi1, hi2, hi3, hi1+hi2+hi3, lo3]
//
//   hi1[s] = sum_{j<8}  Khi[j]  * x[2s-6  + j]      (s < 2051)
//   hi2[s] = sum_{j<22} C2hi[j] * x[4s-18 + j]      (s < 1029)
//   lo3[s] = sum_{j<50} C3lo[j] * x[8s-42 + j]      (s < 518)   (hi3 same taps)
// ---------------------------------------------------------------------------

#define NB     8
#define S0     4096
#define F4     32                          // 128 floats = 32 float4
#define SLOTSZ ((size_t)NB * S0 * F4)      // float4 elems per output slot
#define RT     4                           // s positions per thread
#define GX     128                         // grid.x (S0 / (8 warps * RT))

struct Filt {
    float Klo[8], Khi[8], C2lo[22], C2hi[22], C3lo[50], C3hi[50];
    constexpr Filt()
        : Klo{ 0.23037781330885523f,  0.7148465705525415f,   0.6308807679295904f,
              -0.02798376941698385f, -0.18703481171888114f,  0.030841381835986965f,
               0.032883011666982945f, -0.010597401784997278f },
          Khi{ -0.010597401784997278f, 0.032883011666982945f, 0.030841381835986965f,
                0.18703481171888114f, -0.02798376941698385f, -0.6308807679295904f,
                0.7148465705525415f,  -0.23037781330885523f },
          C2lo{}, C2hi{}, C3lo{}, C3hi{} {
        for (int j = 0; j < 22; ++j) {
            float alo = 0.f, ahi = 0.f;
            for (int u = 0; u < 8; ++u) {
                const int t = j - 2 * u;
                if (t >= 0 && t < 8) { alo += Klo[u] * Klo[t]; ahi += Khi[u] * Klo[t]; }
            }
            C2lo[j] = alo; C2hi[j] = ahi;
        }
        for (int j = 0; j < 50; ++j) {
            float alo = 0.f, ahi = 0.f;
            for (int v = 0; v < 8; ++v) {
                const int t = j - 4 * v;
                if (t >= 0 && t < 22) { alo += Klo[v] * C2lo[t]; ahi += Khi[v] * C2lo[t]; }
            }
            C3lo[j] = alo; C3hi[j] = ahi;
        }
    }
};
__constant__ Filt FF = Filt();

__device__ __forceinline__ void fma4(float4& a, float c, const float4& v) {
    a.x = fmaf(c, v.x, a.x); a.y = fmaf(c, v.y, a.y);
    a.z = fmaf(c, v.z, a.z); a.w = fmaf(c, v.w, a.w);
}
__device__ __forceinline__ void add4(float4& a, const float4& v) {
    a.x += v.x; a.y += v.y; a.z += v.z; a.w += v.w;
}
__device__ __forceinline__ float4 zero4() { return make_float4(0.f, 0.f, 0.f, 0.f); }

__global__ __launch_bounds__(256)
void wavelet_bal_k(const float4* __restrict__ x, float4* __restrict__ out) {
    const int f4 = threadIdx.x;                                   // 0..31
    // Balanced mapping: warp y of block bx covers s-octant y.
    const int sb = (threadIdx.y * GX + blockIdx.x) * RT;          // first s
    const int b  = blockIdx.y;

    const float4* __restrict__ xb = x + (size_t)b * (S0 * F4) + f4;
    const size_t obase = ((size_t)(b * S0 + sb)) * F4 + f4;

    float4 hf[RT];
#pragma unroll
    for (int r = 0; r < RT; ++r) hf[r] = zero4();

    // ---------------- level 1: hi1 -> slot 1 (len 2051) ----------------
    {
        float4 acc[RT];
#pragma unroll
        for (int r = 0; r < RT; ++r) acc[r] = zero4();
        const int base = 2 * sb - 6;                      // span 14
        if (base >= 0 && base + 14 <= S0) {               // interior
#pragma unroll
            for (int k = 0; k < 14; ++k) {
                const float4 v = __ldg(xb + (size_t)(base + k) * F4);
#pragma unroll
                for (int r = 0; r < RT; ++r) {
                    const int j = k - 2 * r;
                    if (j >= 0 && j < 8) fma4(acc[r], FF.Khi[j], v);
                }
            }
        } else if (sb < 2051) {                           // boundary
#pragma unroll
            for (int k = 0; k < 14; ++k) {
                const int xs = base + k;
                if (xs >= 0 && xs < S0) {
                    const float4 v = __ldg(xb + (size_t)xs * F4);
#pragma unroll
                    for (int r = 0; r < RT; ++r) {
                        const int j = k - 2 * r;
                        if (j >= 0 && j < 8 && (sb + r) < 2051)
                            fma4(acc[r], FF.Khi[j], v);
                    }
                }
            }
        }
#pragma unroll
        for (int r = 0; r < RT; ++r) {
            __stcs(out + 1 * SLOTSZ + obase + (size_t)r * F4, acc[r]);
            add4(hf[r], acc[r]);
        }
    }

    // ---------------- level 2: hi2 -> slot 2 (len 1029) ----------------
    {
        float4 acc[RT];
#pragma unroll
        for (int r = 0; r < RT; ++r) acc[r] = zero4();
        const int base = 4 * sb - 18;                     // span 34
        if (base >= 0 && base + 34 <= S0) {               // interior
#pragma unroll
            for (int k = 0; k < 34; ++k) {
                const float4 v = __ldg(xb + (size_t)(base + k) * F4);
#pragma unroll
                for (int r = 0; r < RT; ++r) {
                    const int j = k - 4 * r;
                    if (j >= 0 && j < 22) fma4(acc[r], FF.C2hi[j], v);
                }
            }
        } else if (sb < 1029) {                           // boundary
#pragma unroll
            for (int k = 0; k < 34; ++k) {
                const int xs = base + k;
                if (xs >= 0 && xs < S0) {
                    const float4 v = __ldg(xb + (size_t)xs * F4);
#pragma unroll
                    for (int r = 0; r < RT; ++r) {
                        const int j = k - 4 * r;
                        if (j >= 0 && j < 22 && (sb + r) < 1029)
                            fma4(acc[r], FF.C2hi[j], v);
                    }
                }
            }
        }
#pragma unroll
        for (int r = 0; r < RT; ++r) {
            __stcs(out + 2 * SLOTSZ + obase + (size_t)r * F4, acc[r]);
            add4(hf[r], acc[r]);
        }
    }

    // -------- level 3: lo3 -> slots 0,5 ; hi3 -> slot 3 (len 518) --------
    {
        float4 al[RT], ah[RT];
#pragma unroll
        for (int r = 0; r < RT; ++r) { al[r] = zero4(); ah[r] = zero4(); }
        const int base = 8 * sb - 42;                     // span 74
        if (base >= 0 && base + 74 <= S0) {               // interior
#pragma unroll
            for (int k = 0; k < 74; ++k) {
                const float4 v = __ldg(xb + (size_t)(base + k) * F4);
#pragma unroll
                for (int r = 0; r < RT; ++r) {
                    const int j = k - 8 * r;
                    if (j >= 0 && j < 50) {
                        fma4(al[r], FF.C3lo[j], v);
                        fma4(ah[r], FF.C3hi[j], v);
                    }
                }
            }
        } else if (sb < 518) {                            // boundary
#pragma unroll
            for (int k = 0; k < 74; ++k) {
                const int xs = base + k;
                if (xs >= 0 && xs < S0) {
                    const float4 v = __ldg(xb + (size_t)xs * F4);
#pragma unroll
                    for (int r = 0; r < RT; ++r) {
                        const int j = k - 8 * r;
                        if (j >= 0 && j < 50 && (sb + r) < 518) {
                            fma4(al[r], FF.C3lo[j], v);
                            fma4(ah[r], FF.C3hi[j], v);
                        }
                    }
                }
            }
        }
#pragma unroll
        for (int r = 0; r < RT; ++r) {
            const size_t o = obase + (size_t)r * F4;
            __stcs(out + 0 * SLOTSZ + o, al[r]);
            __stcs(out + 3 * SLOTSZ + o, ah[r]);
            __stcs(out + 5 * SLOTSZ + o, al[r]);
            add4(hf[r], ah[r]);
        }
    }

    // ---------------- slot 4: hi1 + hi2 + hi3 ----------------
#pragma unroll
    for (int r = 0; r < RT; ++r)
        __stcs(out + 4 * SLOTSZ + obase + (size_t)r * F4, hf[r]);
}

extern "C" void kernel_launch(void* const* d_in, const int* in_sizes, int n_in,
                              void* d_out, int out_size) {
    const float4* x = (const float4*)d_in[0];
    float4* out     = (float4*)d_out;

    const dim3 blk(32, 8);                       // 256 threads
    wavelet_bal_k<<<dim3(GX, NB), blk>>>(x, out);
}

// round 10
// speedup vs baseline: 1.3194x; 1.3194x over previous
#include <cuda_runtime.h>

// ---------------------------------------------------------------------------
// LearnableWaveletTransform, fused + s-register-tiled (RT=4 outputs/thread).
// Contiguous warp->s mapping (heavy warps grouped per block — measured best),
// 128-thread blocks + reg cap for 8 blocks/SM occupancy.
//
//   x: [B=8, S=4096, F=128] f32  ->  out: [6, B, 4096, F] f32
//   slots: [lo3, hi1, hi2, hi3, hi1+hi2+hi3, lo3]
//
//   hi1[s] = sum_{j<8}  Khi[j]  * x[2s-6  + j]      (s < 2051)
//   hi2[s] = sum_{j<22} C2hi[j] * x[4s-18 + j]      (s < 1029)
//   lo3[s] = sum_{j<50} C3lo[j] * x[8s-42 + j]      (s < 518)   (hi3 same taps)
// ---------------------------------------------------------------------------

#define NB     8
#define S0     4096
#define F4     32                          // 128 floats = 32 float4
#define SLOTSZ ((size_t)NB * S0 * F4)      // float4 elems per output slot
#define RT     4                           // s positions per thread
#define WPB    4                           // warps per block
#define TS     (WPB * RT)                  // s positions per block = 16

struct Filt {
    float Klo[8], Khi[8], C2lo[22], C2hi[22], C3lo[50], C3hi[50];
    constexpr Filt()
        : Klo{ 0.23037781330885523f,  0.7148465705525415f,   0.6308807679295904f,
              -0.02798376941698385f, -0.18703481171888114f,  0.030841381835986965f,
               0.032883011666982945f, -0.010597401784997278f },
          Khi{ -0.010597401784997278f, 0.032883011666982945f, 0.030841381835986965f,
                0.18703481171888114f, -0.02798376941698385f, -0.6308807679295904f,
                0.7148465705525415f,  -0.23037781330885523f },
          C2lo{}, C2hi{}, C3lo{}, C3hi{} {
        for (int j = 0; j < 22; ++j) {
            float alo = 0.f, ahi = 0.f;
            for (int u = 0; u < 8; ++u) {
                const int t = j - 2 * u;
                if (t >= 0 && t < 8) { alo += Klo[u] * Klo[t]; ahi += Khi[u] * Klo[t]; }
            }
            C2lo[j] = alo; C2hi[j] = ahi;
        }
        for (int j = 0; j < 50; ++j) {
            float alo = 0.f, ahi = 0.f;
            for (int v = 0; v < 8; ++v) {
                const int t = j - 4 * v;
                if (t >= 0 && t < 22) { alo += Klo[v] * C2lo[t]; ahi += Khi[v] * C2lo[t]; }
            }
            C3lo[j] = alo; C3hi[j] = ahi;
        }
    }
};
__constant__ Filt FF = Filt();

__device__ __forceinline__ void fma4(float4& a, float c, const float4& v) {
    a.x = fmaf(c, v.x, a.x); a.y = fmaf(c, v.y, a.y);
    a.z = fmaf(c, v.z, a.z); a.w = fmaf(c, v.w, a.w);
}
__device__ __forceinline__ void add4(float4& a, const float4& v) {
    a.x += v.x; a.y += v.y; a.z += v.z; a.w += v.w;
}
__device__ __forceinline__ float4 zero4() { return make_float4(0.f, 0.f, 0.f, 0.f); }

__global__ __launch_bounds__(128, 8)
void wavelet_occ_k(const float4* __restrict__ x, float4* __restrict__ out) {
    const int f4 = threadIdx.x;                            // 0..31
    const int sb = blockIdx.x * TS + threadIdx.y * RT;     // contiguous mapping
    const int b  = blockIdx.y;

    const float4* __restrict__ xb = x + (size_t)b * (S0 * F4) + f4;
    const size_t obase = ((size_t)(b * S0 + sb)) * F4 + f4;

    float4 hf[RT];
#pragma unroll
    for (int r = 0; r < RT; ++r) hf[r] = zero4();

    // -------- level 3 first: lo3 -> slots 0,5 ; hi3 -> slot 3 (len 518) ----
    {
        float4 al[RT], ah[RT];
#pragma unroll
        for (int r = 0; r < RT; ++r) { al[r] = zero4(); ah[r] = zero4(); }
        const int base = 8 * sb - 42;                     // span 74
        if (base >= 0 && base + 74 <= S0) {               // interior
#pragma unroll
            for (int k = 0; k < 74; ++k) {
                const float4 v = __ldg(xb + (size_t)(base + k) * F4);
#pragma unroll
                for (int r = 0; r < RT; ++r) {
                    const int j = k - 8 * r;
                    if (j >= 0 && j < 50) {
                        fma4(al[r], FF.C3lo[j], v);
                        fma4(ah[r], FF.C3hi[j], v);
                    }
                }
            }
        } else if (sb < 518) {                            // boundary
#pragma unroll
            for (int k = 0; k < 74; ++k) {
                const int xs = base + k;
                if (xs >= 0 && xs < S0) {
                    const float4 v = __ldg(xb + (size_t)xs * F4);
#pragma unroll
                    for (int r = 0; r < RT; ++r) {
                        const int j = k - 8 * r;
                        if (j >= 0 && j < 50 && (sb + r) < 518) {
                            fma4(al[r], FF.C3lo[j], v);
                            fma4(ah[r], FF.C3hi[j], v);
                        }
                    }
                }
            }
        }
#pragma unroll
        for (int r = 0; r < RT; ++r) {
            const size_t o = obase + (size_t)r * F4;
            __stcs(out + 0 * SLOTSZ + o, al[r]);
            __stcs(out + 3 * SLOTSZ + o, ah[r]);
            __stcs(out + 5 * SLOTSZ + o, al[r]);
            add4(hf[r], ah[r]);
        }
    }

    // ---------------- level 2: hi2 -> slot 2 (len 1029) ----------------
    {
        float4 acc[RT];
#pragma unroll
        for (int r = 0; r < RT; ++r) acc[r] = zero4();
        const int base = 4 * sb - 18;                     // span 34
        if (base >= 0 && base + 34 <= S0) {               // interior
#pragma unroll
            for (int k = 0; k < 34; ++k) {
                const float4 v = __ldg(xb + (size_t)(base + k) * F4);
#pragma unroll
                for (int r = 0; r < RT; ++r) {
                    const int j = k - 4 * r;
                    if (j >= 0 && j < 22) fma4(acc[r], FF.C2hi[j], v);
                }
            }
        } else if (sb < 1029) {                           // boundary
#pragma unroll
            for (int k = 0; k < 34; ++k) {
                const int xs = base + k;
                if (xs >= 0 && xs < S0) {
                    const float4 v = __ldg(xb + (size_t)xs * F4);
#pragma unroll
                    for (int r = 0; r < RT; ++r) {
                        const int j = k - 4 * r;
                        if (j >= 0 && j < 22 && (sb + r) < 1029)
                            fma4(acc[r], FF.C2hi[j], v);
                    }
                }
            }
        }
#pragma unroll
        for (int r = 0; r < RT; ++r) {
            __stcs(out + 2 * SLOTSZ + obase + (size_t)r * F4, acc[r]);
            add4(hf[r], acc[r]);
        }
    }

    // ---------------- level 1: hi1 -> slot 1 (len 2051) ----------------
    {
        float4 acc[RT];
#pragma unroll
        for (int r = 0; r < RT; ++r) acc[r] = zero4();
        const int base = 2 * sb - 6;                      // span 14
        if (base >= 0 && base + 14 <= S0) {               // interior
#pragma unroll
            for (int k = 0; k < 14; ++k) {
                const float4 v = __ldg(xb + (size_t)(base + k) * F4);
#pragma unroll
                for (int r = 0; r < RT; ++r) {
                    const int j = k - 2 * r;
                    if (j >= 0 && j < 8) fma4(acc[r], FF.Khi[j], v);
                }
            }
        } else if (sb < 2051) {                           // boundary
#pragma unroll
            for (int k = 0; k < 14; ++k) {
                const int xs = base + k;
                if (xs >= 0 && xs < S0) {
                    const float4 v = __ldg(xb + (size_t)xs * F4);
#pragma unroll
                    for (int r = 0; r < RT; ++r) {
                        const int j = k - 2 * r;
                        if (j >= 0 && j < 8 && (sb + r) < 2051)
                            fma4(acc[r], FF.Khi[j], v);
                    }
                }
            }
        }
#pragma unroll
        for (int r = 0; r < RT; ++r) {
            __stcs(out + 1 * SLOTSZ + obase + (size_t)r * F4, acc[r]);
            add4(hf[r], acc[r]);
        }
    }

    // ---------------- slot 4: hi1 + hi2 + hi3 ----------------
#pragma unroll
    for (int r = 0; r < RT; ++r)
        __stcs(out + 4 * SLOTSZ + obase + (size_t)r * F4, hf[r]);
}

extern "C" void kernel_launch(void* const* d_in, const int* in_sizes, int n_in,
                              void* d_out, int out_size) {
    const float4* x = (const float4*)d_in[0];
    float4* out     = (float4*)d_out;

    const dim3 blk(32, WPB);                     // 128 threads
    wavelet_occ_k<<<dim3(S0 / TS, NB), blk>>>(x, out);
}